// round 1
// baseline (speedup 1.0000x reference)
#include <cuda_runtime.h>
#include <cuda_bf16.h>

// Problem constants (compile-time, from reference):
//   B = 8192 rows, T = 4096 features, G = 64 groups.
//   Group sizes cycle (32, 64, 96, 64) x 16 cycles. Cycle = 256 elements.
//   All group boundaries are multiples of 32 -> every aligned 32-elem chunk
//   belongs to exactly one group. 128 chunks per row.
//
// Output layout: d_out[0 .. B)           = Z  (fp32)
//                d_out[B .. B + B*64)    = a  (fp32, row-major [B, 64])

#define T_DIM   4096
#define G_DIM   64
#define NTHREADS 256

__global__ __launch_bounds__(NTHREADS)
void agp_kernel(const float* __restrict__ H,
                const float* __restrict__ score_w,
                const float* __restrict__ score_b,
                float* __restrict__ out, int B)
{
    const int b   = blockIdx.x;
    const int tid = threadIdx.x;

    __shared__ float chunk_sum[T_DIM / 32];   // 128 chunk sums
    __shared__ float s_w, s_b;
    if (tid == 0) { s_w = score_w[0]; s_b = score_b[0]; }

    const float4* row4 = reinterpret_cast<const float4*>(H + (size_t)b * T_DIM);

    // --- Phase 1: load 16KB row, reduce to 128 chunk sums (no atomics) ---
    // Each thread: 4 coalesced float4 loads at element offsets 4*tid + 1024*k.
    // A float4 never crosses a 32-elem boundary, so each belongs to one chunk.
    #pragma unroll
    for (int k = 0; k < 4; ++k) {
        float4 v = row4[tid + NTHREADS * k];
        float s = (v.x + v.y) + (v.z + v.w);
        // butterfly reduce within aligned 8-lane subgroup -> 32-elem chunk sum
        s += __shfl_xor_sync(0xffffffffu, s, 1);
        s += __shfl_xor_sync(0xffffffffu, s, 2);
        s += __shfl_xor_sync(0xffffffffu, s, 4);
        if ((tid & 7) == 0) {
            int chunk = (tid >> 3) + 32 * k;   // = (4*tid + 1024*k) / 32
            chunk_sum[chunk] = s;
        }
    }
    __syncthreads();

    // --- Phase 2: warp 0 does groups -> softmax -> Z ---
    if (tid < 32) {
        const float w = s_w, bias = s_b;
        // per-subgroup (g & 3): chunk start within cycle, chunk count, size
        const int   c_start[4] = {0, 1, 3, 6};
        const int   c_cnt[4]   = {1, 2, 3, 2};
        const float inv_sz[4]  = {1.0f/32.0f, 1.0f/64.0f, 1.0f/96.0f, 1.0f/64.0f};

        float Gm[2];   // group means for g = tid, g = tid + 32
        float sc[2];   // scores
        #pragma unroll
        for (int j = 0; j < 2; ++j) {
            int g    = tid + 32 * j;
            int sub  = g & 3;
            int base = (g >> 2) * 8 + c_start[sub];
            float s = 0.0f;
            #pragma unroll
            for (int c = 0; c < 3; ++c)
                if (c < c_cnt[sub]) s += chunk_sum[base + c];
            Gm[j] = s * inv_sz[sub];
            sc[j] = Gm[j] * w + bias;
        }

        // softmax over 64 values (2 per lane)
        float mx = fmaxf(sc[0], sc[1]);
        #pragma unroll
        for (int d = 16; d > 0; d >>= 1)
            mx = fmaxf(mx, __shfl_xor_sync(0xffffffffu, mx, d));

        float p0 = expf(sc[0] - mx);
        float p1 = expf(sc[1] - mx);
        float ssum = p0 + p1;
        #pragma unroll
        for (int d = 16; d > 0; d >>= 1)
            ssum += __shfl_xor_sync(0xffffffffu, ssum, d);
        float inv = 1.0f / ssum;
        float a0 = p0 * inv;
        float a1 = p1 * inv;

        float zp = a0 * Gm[0] + a1 * Gm[1];
        #pragma unroll
        for (int d = 16; d > 0; d >>= 1)
            zp += __shfl_xor_sync(0xffffffffu, zp, d);

        // write outputs: Z at [0,B), a at [B, B + B*64)
        float* a_out = out + B + (size_t)b * G_DIM;
        a_out[tid]      = a0;
        a_out[tid + 32] = a1;
        if (tid == 0) out[b] = zp;
    }
}

extern "C" void kernel_launch(void* const* d_in, const int* in_sizes, int n_in,
                              void* d_out, int out_size)
{
    const float* H  = (const float*)d_in[0];   // [B, 4096]
    const float* sw = (const float*)d_in[1];   // [1,1]
    const float* sb = (const float*)d_in[2];   // [1]
    float* out = (float*)d_out;

    int B = in_sizes[0] / T_DIM;               // 8192
    agp_kernel<<<B, NTHREADS>>>(H, sw, sb, out, B);
}